// round 1
// baseline (speedup 1.0000x reference)
#include <cuda_runtime.h>
#include <math.h>

#define HID   2048
#define HID3  6144
#define NH    16
#define HD    128
#define BATCH 4
#define SEQ   2048
#define MROWS (BATCH*SEQ)   // 8192

// ---------------- scratch (no allocations allowed) ----------------
__device__ float g_qkv[(long long)MROWS * HID3];   // 201 MB
__device__ float g_attn[(long long)MROWS * HID];   // 64 MB

// ---------------- packed f32x2 helpers (Blackwell FFMA2 path) ----------------
__device__ __forceinline__ unsigned long long pk2(float x, float y) {
    unsigned long long r;
    asm("mov.b64 %0, {%1, %2};" : "=l"(r)
        : "r"(__float_as_uint(x)), "r"(__float_as_uint(y)));
    return r;
}
__device__ __forceinline__ void fma2(unsigned long long& d,
                                     unsigned long long a,
                                     unsigned long long b) {
    asm("fma.rn.f32x2 %0, %1, %2, %0;" : "+l"(d) : "l"(a), "l"(b));
}
__device__ __forceinline__ void mul2(unsigned long long& d,
                                     unsigned long long a) {
    asm("mul.rn.f32x2 %0, %0, %1;" : "+l"(d) : "l"(a));
}
__device__ __forceinline__ float2 unpk2(unsigned long long v) {
    unsigned int lo, hi;
    asm("mov.b64 {%0, %1}, %2;" : "=r"(lo), "=r"(hi) : "l"(v));
    return make_float2(__uint_as_float(lo), __uint_as_float(hi));
}

// ---------------- SGEMM: C[M,N] = A[M,K] * W[N,K]^T + bias[N] ----------------
// 128x128 tile, BK=16, 256 threads, 8x8 microtile via f32x2.
__global__ __launch_bounds__(256) void sgemm_bias_kernel(
    const float* __restrict__ A, const float* __restrict__ W,
    const float* __restrict__ bias, float* __restrict__ C,
    int M, int N, int K)
{
    __shared__ float As[16][132];
    __shared__ float Bs[16][132];
    const int tid = threadIdx.x;
    const int bm = blockIdx.y * 128;
    const int bn = blockIdx.x * 128;
    const int tx = tid & 15;   // 0..15 -> 8 output cols (4 + 4 at +64)
    const int ty = tid >> 4;   // 0..15 -> 8 output rows (4 + 4 at +64)

    unsigned long long c2[8][4];
#pragma unroll
    for (int i = 0; i < 8; i++)
#pragma unroll
        for (int j = 0; j < 4; j++) c2[i][j] = 0ull;

    for (int k0 = 0; k0 < K; k0 += 16) {
        // cooperative load: 128 rows x 16 cols of A and W (transposed into smem)
#pragma unroll
        for (int it = 0; it < 2; it++) {
            int idx = tid + it * 256;          // 0..511
            int r   = idx >> 2;                // 0..127
            int c4  = (idx & 3) * 4;           // 0,4,8,12
            float4 va = *(const float4*)(A + (long long)(bm + r) * K + k0 + c4);
            As[c4 + 0][r] = va.x; As[c4 + 1][r] = va.y;
            As[c4 + 2][r] = va.z; As[c4 + 3][r] = va.w;
            float4 vw = *(const float4*)(W + (long long)(bn + r) * K + k0 + c4);
            Bs[c4 + 0][r] = vw.x; Bs[c4 + 1][r] = vw.y;
            Bs[c4 + 2][r] = vw.z; Bs[c4 + 3][r] = vw.w;
        }
        __syncthreads();

#pragma unroll
        for (int k = 0; k < 16; k++) {
            float4 a0 = *(const float4*)&As[k][ty * 4];
            float4 a1 = *(const float4*)&As[k][64 + ty * 4];
            ulonglong2 b0 = *(const ulonglong2*)&Bs[k][tx * 4];
            ulonglong2 b1 = *(const ulonglong2*)&Bs[k][64 + tx * 4];
            float av[8] = {a0.x, a0.y, a0.z, a0.w, a1.x, a1.y, a1.z, a1.w};
            unsigned long long bv[4] = {b0.x, b0.y, b1.x, b1.y};
#pragma unroll
            for (int i = 0; i < 8; i++) {
                unsigned long long aa = pk2(av[i], av[i]);
#pragma unroll
                for (int j = 0; j < 4; j++) fma2(c2[i][j], aa, bv[j]);
            }
        }
        __syncthreads();
    }

    float4 bias0 = *(const float4*)&bias[bn + tx * 4];
    float4 bias1 = *(const float4*)&bias[bn + 64 + tx * 4];
#pragma unroll
    for (int i = 0; i < 8; i++) {
        int m = bm + ((i < 4) ? (ty * 4 + i) : (64 + ty * 4 + i - 4));
        float2 p0 = unpk2(c2[i][0]), p1 = unpk2(c2[i][1]);
        float2 p2 = unpk2(c2[i][2]), p3 = unpk2(c2[i][3]);
        float4 o0 = make_float4(p0.x + bias0.x, p0.y + bias0.y,
                                p1.x + bias0.z, p1.y + bias0.w);
        float4 o1 = make_float4(p2.x + bias1.x, p2.y + bias1.y,
                                p3.x + bias1.z, p3.y + bias1.w);
        *(float4*)(C + (long long)m * N + bn + tx * 4)      = o0;
        *(float4*)(C + (long long)m * N + bn + 64 + tx * 4) = o1;
    }
}

// ---------------- causal flash attention ----------------
// grid (SEQ/128, NH, BATCH), 128 threads; thread t owns query row qb*128+t.
// Q tile swizzled in smem (conflict-free per-thread LDS.128); K/V broadcast.
// Probs go through a thread-private smem column to allow dynamic-j PV loop
// while keeping the 128-wide accumulator fully in (packed) registers.
__global__ __launch_bounds__(128) void attn_kernel()
{
    extern __shared__ float smf[];
    float* Qs = smf;            // 128*128 (swizzled)
    float* Ks = smf + 16384;    // 32*128
    float* Vs = smf + 20480;    // 32*128
    float* Ps = smf + 24576;    // 128*33 (thread-private rows)

    const int t  = threadIdx.x;
    const int qb = blockIdx.x, h = blockIdx.y, b = blockIdx.z;
    const int row0 = b * SEQ + qb * 128;
    const float* Qg = g_qkv + (long long)row0 * HID3 + h * HD;
    const float* Kg = g_qkv + (long long)(b * SEQ) * HID3 + HID     + h * HD;
    const float* Vg = g_qkv + (long long)(b * SEQ) * HID3 + 2 * HID + h * HD;

    // load Q tile (swizzled: col ^= (row&7)<<2, in float units)
    for (int i = t; i < 4096; i += 128) {
        int r = i >> 5, c4 = (i & 31) * 4;
        float4 v = *(const float4*)(Qg + (long long)r * HID3 + c4);
        int col = c4 ^ ((r & 7) << 2);
        *(float4*)&Qs[r * 128 + col] = v;
    }

    unsigned long long acc2[64];
#pragma unroll
    for (int i = 0; i < 64; i++) acc2[i] = 0ull;
    float mrow = -1e30f, lrow = 0.f;
    const int   qi    = qb * 128 + t;
    const int   sw    = (t & 7) << 2;
    const int   nkb   = (qb + 1) * 4;           // 32-wide key blocks (causal)
    const float scale = 0.08838834764831845f;   // 1/sqrt(128)
    const float NEGINF = __int_as_float(0xff800000);

    for (int kb = 0; kb < nkb; kb++) {
        __syncthreads();
        for (int i = t; i < 1024; i += 128) {
            int r = i >> 5, c4 = (i & 31) * 4;
            *(float4*)&Ks[r * 128 + c4] =
                *(const float4*)(Kg + (long long)(kb * 32 + r) * HID3 + c4);
            *(float4*)&Vs[r * 128 + c4] =
                *(const float4*)(Vg + (long long)(kb * 32 + r) * HID3 + c4);
        }
        __syncthreads();

        // S = Q K^T for 32 keys (two halves of 16 to cap register pressure)
        float sv[32];
#pragma unroll
        for (int half = 0; half < 2; half++) {
            unsigned long long s2[16];
#pragma unroll
            for (int jj = 0; jj < 16; jj++) s2[jj] = 0ull;
            for (int kc = 0; kc < 128; kc += 4) {
                ulonglong2 q2 = *(const ulonglong2*)&Qs[t * 128 + (kc ^ sw)];
#pragma unroll
                for (int jj = 0; jj < 16; jj++) {
                    int j = half * 16 + jj;
                    ulonglong2 k2 = *(const ulonglong2*)&Ks[j * 128 + kc];
                    fma2(s2[jj], q2.x, k2.x);
                    fma2(s2[jj], q2.y, k2.y);
                }
            }
#pragma unroll
            for (int jj = 0; jj < 16; jj++) {
                float2 p = unpk2(s2[jj]);
                sv[half * 16 + jj] = (p.x + p.y) * scale;
            }
        }

        // online softmax update
        const int kbase = kb * 32;
        float mnew = mrow;
#pragma unroll
        for (int j = 0; j < 32; j++) {
            float v = (kbase + j <= qi) ? sv[j] : NEGINF;
            sv[j] = v;
            mnew = fmaxf(mnew, v);
        }
        float alpha = __expf(mrow - mnew);
        mrow = mnew;
        float lsum = 0.f;
#pragma unroll
        for (int j = 0; j < 32; j++) {
            float p = __expf(sv[j] - mnew);
            lsum += p;
            Ps[t * 33 + j] = p;     // thread-private; no sync needed
        }
        lrow = lrow * alpha + lsum;

        unsigned long long al2 = pk2(alpha, alpha);
#pragma unroll
        for (int i = 0; i < 64; i++) mul2(acc2[i], al2);

        // O += P V  (dynamic j, literal-indexed packed accumulator)
        for (int j = 0; j < 32; j++) {
            float p = Ps[t * 33 + j];
            unsigned long long pp = pk2(p, p);
#pragma unroll
            for (int kc = 0; kc < 128; kc += 4) {
                ulonglong2 vv = *(const ulonglong2*)&Vs[j * 128 + kc];
                fma2(acc2[kc >> 1], pp, vv.x);
                fma2(acc2[(kc >> 1) + 1], pp, vv.y);
            }
        }
    }

    float inv = 1.f / lrow;
    float* Og = g_attn + (long long)(row0 + t) * HID + h * HD;
#pragma unroll
    for (int k = 0; k < 64; k += 2) {
        float2 x = unpk2(acc2[k]), y = unpk2(acc2[k + 1]);
        *(float4*)&Og[k * 2] =
            make_float4(x.x * inv, x.y * inv, y.x * inv, y.y * inv);
    }
}

// ---------------- launch ----------------
extern "C" void kernel_launch(void* const* d_in, const int* in_sizes, int n_in,
                              void* d_out, int out_size)
{
    (void)in_sizes; (void)n_in; (void)out_size;
    const float* x       = (const float*)d_in[0];
    const float* w_qkv   = (const float*)d_in[1];
    const float* b_qkv   = (const float*)d_in[2];
    const float* w_dense = (const float*)d_in[3];
    const float* b_dense = (const float*)d_in[4];
    float* out = (float*)d_out;

    float *qkv_buf, *attn_buf;
    cudaGetSymbolAddress((void**)&qkv_buf, g_qkv);
    cudaGetSymbolAddress((void**)&attn_buf, g_attn);

    const int ATTN_SMEM = (16384 + 4096 + 4096 + 128 * 33) * 4;  // 115200 B
    cudaFuncSetAttribute(attn_kernel,
                         cudaFuncAttributeMaxDynamicSharedMemorySize, ATTN_SMEM);

    // 1) QKV = X @ Wqkv^T + b
    sgemm_bias_kernel<<<dim3(HID3 / 128, MROWS / 128), 256>>>(
        x, w_qkv, b_qkv, qkv_buf, MROWS, HID3, HID);

    // 2) causal flash attention
    attn_kernel<<<dim3(SEQ / 128, NH, BATCH), 128, ATTN_SMEM>>>();

    // 3) out = attn @ Wdense^T + b
    sgemm_bias_kernel<<<dim3(HID / 128, MROWS / 128), 256>>>(
        attn_buf, w_dense, b_dense, out, MROWS, HID, HID);
}

// round 4
// speedup vs baseline: 1.5773x; 1.5773x over previous
#include <cuda_runtime.h>
#include <cuda_bf16.h>
#include <cstdint>
#include <math.h>

#define HID   2048
#define HID3  6144
#define NH    16
#define HD    128
#define BATCH 4
#define SEQ   2048
#define MROWS 8192
#define K2    4096          // storage: [hi | lo] bf16 per row
#define BKG   64            // bf16 k-chunk per stage (128B rows)
#define NCHT  96            // 3-term split: Ah*Bh + Al*Bh + Ah*Bl
#define GSTAGES 3
#define STG_BYTES 32768     // 16KB A + 16KB B per stage
#define GEMM_SMEM (GSTAGES*STG_BYTES)   // 98304

// ---------------- scratch (no allocations allowed) ----------------
__device__ float g_qkv[(size_t)MROWS * HID3];
__device__ float g_attn[(size_t)MROWS * HID];
__device__ __nv_bfloat16 g_xc[(size_t)MROWS * K2];
__device__ __nv_bfloat16 g_wqkvc[(size_t)HID3 * K2];
__device__ __nv_bfloat16 g_wdc[(size_t)HID * K2];
__device__ __nv_bfloat16 g_attnc[(size_t)MROWS * K2];

// ---------------- helpers ----------------
__device__ __forceinline__ uint32_t s2u(const void* p) {
    uint32_t a;
    asm("{ .reg .u64 t; cvta.to.shared.u64 t, %1; cvt.u32.u64 %0, t; }"
        : "=r"(a) : "l"(p));
    return a;
}
__device__ __forceinline__ void cp16(uint32_t dst, const void* src) {
    asm volatile("cp.async.cg.shared.global [%0], [%1], 16;"
                 :: "r"(dst), "l"(src));
}
__device__ __forceinline__ void ldsm4(uint32_t* r, uint32_t addr) {
    asm volatile("ldmatrix.sync.aligned.m8n8.x4.shared.b16 {%0,%1,%2,%3}, [%4];"
        : "=r"(r[0]), "=r"(r[1]), "=r"(r[2]), "=r"(r[3]) : "r"(addr));
}
__device__ __forceinline__ void mma16816(float* c, const uint32_t* a,
                                         uint32_t b0, uint32_t b1) {
    asm volatile("mma.sync.aligned.m16n8k16.row.col.f32.bf16.bf16.f32 "
        "{%0,%1,%2,%3}, {%4,%5,%6,%7}, {%8,%9}, {%0,%1,%2,%3};"
        : "+f"(c[0]), "+f"(c[1]), "+f"(c[2]), "+f"(c[3])
        : "r"(a[0]), "r"(a[1]), "r"(a[2]), "r"(a[3]), "r"(b0), "r"(b1));
}

// ---------------- split conversion: fp32[rows][2048] -> bf16[rows][hi|lo] ------
__global__ __launch_bounds__(256) void split_kernel(const float* __restrict__ in,
                                                    __nv_bfloat16* __restrict__ out,
                                                    int rows)
{
    size_t i = (size_t)blockIdx.x * 256 + threadIdx.x;
    size_t n4 = (size_t)rows * HID / 4;
    if (i >= n4) return;
    size_t e = i * 4;
    size_t r = e >> 11;
    int    c = (int)(e & 2047);
    float4 v = ((const float4*)in)[i];
    __nv_bfloat16 h0 = __float2bfloat16(v.x), h1 = __float2bfloat16(v.y);
    __nv_bfloat16 h2 = __float2bfloat16(v.z), h3 = __float2bfloat16(v.w);
    __nv_bfloat16 l0 = __float2bfloat16(v.x - __bfloat162float(h0));
    __nv_bfloat16 l1 = __float2bfloat16(v.y - __bfloat162float(h1));
    __nv_bfloat16 l2 = __float2bfloat16(v.z - __bfloat162float(h2));
    __nv_bfloat16 l3 = __float2bfloat16(v.w - __bfloat162float(h3));
    ushort4 hv = make_ushort4(__bfloat16_as_ushort(h0), __bfloat16_as_ushort(h1),
                              __bfloat16_as_ushort(h2), __bfloat16_as_ushort(h3));
    ushort4 lv = make_ushort4(__bfloat16_as_ushort(l0), __bfloat16_as_ushort(l1),
                              __bfloat16_as_ushort(l2), __bfloat16_as_ushort(l3));
    __nv_bfloat16* o = out + r * K2;
    *(ushort4*)(o + c)       = hv;
    *(ushort4*)(o + HID + c) = lv;
}

// ---------------- HMMA GEMM: C[M,N] = A[M,·]@B[N,·]^T + bias (bf16x3 split) ----
// 128x128 tile, BK=64, 3-stage cp.async, mma.sync m16n8k16 bf16.
__global__ __launch_bounds__(256, 2) void gemm_hmma_kernel(
    const __nv_bfloat16* __restrict__ A, const __nv_bfloat16* __restrict__ B,
    const float* __restrict__ bias, float* __restrict__ C, int Ncols)
{
    extern __shared__ char sm[];
    const uint32_t sb = s2u(sm);
    const int tid = threadIdx.x;
    const int wid = tid >> 5, lane = tid & 31;
    const size_t bm = (size_t)blockIdx.y * 128;
    const size_t bn = (size_t)blockIdx.x * 128;
    const int wm = wid & 3, wn = wid >> 2;

    // k-chunk indirection for the 3-term split:
    //   ch 0..31 : Ah*Bh   ch 32..63 : Al*Bh   ch 64..95 : Ah*Bl
    auto issue = [&](int ch) {
        int ach = (ch < 64) ? ch : (ch - 64);          // [Ah | Al | Ah]
        int bch = (ch < 32) ? ch : (ch - 32);          // [Bh | Bh | Bl]
        uint32_t st = sb + (ch % GSTAGES) * STG_BYTES;
        const __nv_bfloat16* Ab = A + (size_t)ach * BKG;
        const __nv_bfloat16* Bb = B + (size_t)bch * BKG;
#pragma unroll
        for (int i = 0; i < 4; i++) {
            int u = i * 256 + tid;                     // 0..1023
            int r = u >> 3, c = u & 7;
            uint32_t sw = (uint32_t)(r * 128) + (uint32_t)((c * 16) ^ ((r & 7) << 4));
            cp16(st + sw,         Ab + (bm + r) * K2 + c * 8);
            cp16(st + 16384 + sw, Bb + (bn + r) * K2 + c * 8);
        }
        asm volatile("cp.async.commit_group;");
    };

    issue(0);
    issue(1);

    float acc[2][8][4];
#pragma unroll
    for (int mi = 0; mi < 2; mi++)
#pragma unroll
        for (int ni = 0; ni < 8; ni++)
#pragma unroll
            for (int q = 0; q < 4; q++) acc[mi][ni][q] = 0.f;

    const int lm_row = lane & 15;
    const int lm_hi  = (lane >> 4) << 4;

    for (int ch = 0; ch < NCHT; ch++) {
        asm volatile("cp.async.wait_group 1;");
        __syncthreads();
        if (ch + 2 < NCHT) issue(ch + 2);
        uint32_t st = sb + (ch % GSTAGES) * STG_BYTES;
#pragma unroll
        for (int kk = 0; kk < 64; kk += 16) {
            uint32_t a[2][4];
#pragma unroll
            for (int mi = 0; mi < 2; mi++) {
                int row = wm * 32 + mi * 16 + lm_row;
                uint32_t byte = (uint32_t)(kk * 2 + lm_hi);
                ldsm4(a[mi], st + row * 128 + (byte ^ ((row & 7) << 4)));
            }
            uint32_t b[4][4];
#pragma unroll
            for (int g = 0; g < 4; g++) {
                int row = wn * 64 + g * 16 + lm_row;
                uint32_t byte = (uint32_t)(kk * 2 + lm_hi);
                ldsm4(b[g], st + 16384 + row * 128 + (byte ^ ((row & 7) << 4)));
            }
            // reg mapping per x4: low-n frag {r0,r2}, hi-n {r1,r3}
#pragma unroll
            for (int mi = 0; mi < 2; mi++)
#pragma unroll
                for (int ni = 0; ni < 8; ni++) {
                    int g = ni >> 1, h = ni & 1;
                    mma16816(acc[mi][ni], a[mi], b[g][h], b[g][h + 2]);
                }
        }
    }

    // epilogue
    const int r0 = wm * 32 + (lane >> 2);
    const int c0 = wn * 64 + (lane & 3) * 2;
#pragma unroll
    for (int mi = 0; mi < 2; mi++)
#pragma unroll
        for (int ni = 0; ni < 8; ni++) {
            size_t col = bn + c0 + ni * 8;
            float2 bv = *(const float2*)(bias + col);
            float* p0 = C + (bm + r0 + mi * 16) * (size_t)Ncols + col;
            float* p1 = p0 + 8 * (size_t)Ncols;
            float2 o0 = make_float2(acc[mi][ni][0] + bv.x, acc[mi][ni][1] + bv.y);
            float2 o1 = make_float2(acc[mi][ni][2] + bv.x, acc[mi][ni][3] + bv.y);
            *(float2*)p0 = o0;
            *(float2*)p1 = o1;
        }
}

// ---------------- packed f32x2 helpers ----------------
__device__ __forceinline__ unsigned long long pk2(float x, float y) {
    unsigned long long r;
    asm("mov.b64 %0, {%1, %2};" : "=l"(r)
        : "r"(__float_as_uint(x)), "r"(__float_as_uint(y)));
    return r;
}
__device__ __forceinline__ void fma2(unsigned long long& d,
                                     unsigned long long a, unsigned long long b) {
    asm("fma.rn.f32x2 %0, %1, %2, %0;" : "+l"(d) : "l"(a), "l"(b));
}
__device__ __forceinline__ void mul2(unsigned long long& d, unsigned long long a) {
    asm("mul.rn.f32x2 %0, %0, %1;" : "+l"(d) : "l"(a));
}
__device__ __forceinline__ float2 unpk2(unsigned long long v) {
    unsigned int lo, hi;
    asm("mov.b64 {%0, %1}, %2;" : "=r"(lo), "=r"(hi) : "l"(v));
    return make_float2(__uint_as_float(lo), __uint_as_float(hi));
}

// ---------------- causal flash attention (fp32, 2 CTA/SM) ----------------
#define ATTN_SMEM 98304   // Qs 64KB + Ks 16KB + Vs 16KB
__global__ __launch_bounds__(128, 2) void attn_kernel()
{
    extern __shared__ float smf[];
    float* Qs = smf;            // 128*128 (swizzled)
    float* Ks = smf + 16384;    // 32*128
    float* Vs = smf + 20480;    // 32*128

    const int t  = threadIdx.x;
    const int qb = blockIdx.x, h = blockIdx.y, b = blockIdx.z;
    const int row0 = b * SEQ + qb * 128;
    const float* Qg = g_qkv + (size_t)row0 * HID3 + h * HD;
    const float* Kg = g_qkv + (size_t)(b * SEQ) * HID3 + HID     + h * HD;
    const float* Vg = g_qkv + (size_t)(b * SEQ) * HID3 + 2 * HID + h * HD;

    for (int i = t; i < 4096; i += 128) {
        int r = i >> 5, c4 = (i & 31) * 4;
        float4 v = *(const float4*)(Qg + (size_t)r * HID3 + c4);
        int col = c4 ^ ((r & 7) << 2);
        *(float4*)&Qs[r * 128 + col] = v;
    }

    unsigned long long acc2[64];
#pragma unroll
    for (int i = 0; i < 64; i++) acc2[i] = 0ull;
    float mrow = -1e30f, lrow = 0.f;
    const int   qi    = qb * 128 + t;
    const int   sw    = (t & 7) << 2;
    const int   nkb   = (qb + 1) * 4;
    const float scale = 0.08838834764831845f;
    const float NEGINF = __int_as_float(0xff800000);

    for (int kb = 0; kb < nkb; kb++) {
        __syncthreads();
        for (int i = t; i < 1024; i += 128) {
            int r = i >> 5, c4 = (i & 31) * 4;
            *(float4*)&Ks[r * 128 + c4] =
                *(const float4*)(Kg + (size_t)(kb * 32 + r) * HID3 + c4);
            *(float4*)&Vs[r * 128 + c4] =
                *(const float4*)(Vg + (size_t)(kb * 32 + r) * HID3 + c4);
        }
        __syncthreads();

        float sv[32];
#pragma unroll
        for (int half = 0; half < 2; half++) {
            unsigned long long s2[16];
#pragma unroll
            for (int jj = 0; jj < 16; jj++) s2[jj] = 0ull;
            for (int kc = 0; kc < 128; kc += 4) {
                ulonglong2 q2 = *(const ulonglong2*)&Qs[t * 128 + (kc ^ sw)];
#pragma unroll
                for (int jj = 0; jj < 16; jj++) {
                    int j = half * 16 + jj;
                    ulonglong2 k2 = *(const ulonglong2*)&Ks[j * 128 + kc];
                    fma2(s2[jj], q2.x, k2.x);
                    fma2(s2[jj], q2.y, k2.y);
                }
            }
#pragma unroll
            for (int jj = 0; jj < 16; jj++) {
                float2 p = unpk2(s2[jj]);
                sv[half * 16 + jj] = (p.x + p.y) * scale;
            }
        }

        const int kbase = kb * 32;
        float mnew = mrow;
#pragma unroll
        for (int j = 0; j < 32; j++) {
            float v = (kbase + j <= qi) ? sv[j] : NEGINF;
            sv[j] = v;
            mnew = fmaxf(mnew, v);
        }
        float alpha = __expf(mrow - mnew);
        mrow = mnew;
        float lsum = 0.f;
#pragma unroll
        for (int j = 0; j < 32; j++) {
            float p = __expf(sv[j] - mnew);
            lsum += p;
            sv[j] = p;               // probs register-resident
        }
        lrow = lrow * alpha + lsum;

        unsigned long long al2 = pk2(alpha, alpha);
#pragma unroll
        for (int i = 0; i < 64; i++) mul2(acc2[i], al2);

        // O += P V  (fully unrolled, static indexing)
#pragma unroll
        for (int j = 0; j < 32; j++) {
            unsigned long long pp = pk2(sv[j], sv[j]);
#pragma unroll
            for (int kc = 0; kc < 128; kc += 4) {
                ulonglong2 vv = *(const ulonglong2*)&Vs[j * 128 + kc];
                fma2(acc2[kc >> 1], pp, vv.x);
                fma2(acc2[(kc >> 1) + 1], pp, vv.y);
            }
        }
    }

    float inv = 1.f / lrow;
    float* Og = g_attn + (size_t)(row0 + t) * HID + h * HD;
#pragma unroll
    for (int k = 0; k < 64; k += 2) {
        float2 x = unpk2(acc2[k]), y = unpk2(acc2[k + 1]);
        *(float4*)&Og[k * 2] =
            make_float4(x.x * inv, x.y * inv, y.x * inv, y.y * inv);
    }
}

// ---------------- launch ----------------
extern "C" void kernel_launch(void* const* d_in, const int* in_sizes, int n_in,
                              void* d_out, int out_size)
{
    (void)in_sizes; (void)n_in; (void)out_size;
    const float* x       = (const float*)d_in[0];
    const float* w_qkv   = (const float*)d_in[1];
    const float* b_qkv   = (const float*)d_in[2];
    const float* w_dense = (const float*)d_in[3];
    const float* b_dense = (const float*)d_in[4];
    float* out = (float*)d_out;

    float *qkv_buf, *attn_buf;
    __nv_bfloat16 *xc, *wqkvc, *wdc, *attnc;
    cudaGetSymbolAddress((void**)&qkv_buf, g_qkv);
    cudaGetSymbolAddress((void**)&attn_buf, g_attn);
    cudaGetSymbolAddress((void**)&xc, g_xc);
    cudaGetSymbolAddress((void**)&wqkvc, g_wqkvc);
    cudaGetSymbolAddress((void**)&wdc, g_wdc);
    cudaGetSymbolAddress((void**)&attnc, g_attnc);

    cudaFuncSetAttribute(attn_kernel,
                         cudaFuncAttributeMaxDynamicSharedMemorySize, ATTN_SMEM);
    cudaFuncSetAttribute(gemm_hmma_kernel,
                         cudaFuncAttributeMaxDynamicSharedMemorySize, GEMM_SMEM);

    // split conversions (fp32 -> bf16 hi|lo)
    split_kernel<<<(MROWS * HID / 4 + 255) / 256, 256>>>(x, xc, MROWS);
    split_kernel<<<(HID3 * HID / 4 + 255) / 256, 256>>>(w_qkv, wqkvc, HID3);
    split_kernel<<<(HID  * HID / 4 + 255) / 256, 256>>>(w_dense, wdc, HID);

    // 1) QKV = X @ Wqkv^T + b   (HMMA bf16x3)
    gemm_hmma_kernel<<<dim3(HID3 / 128, MROWS / 128), 256, GEMM_SMEM>>>(
        xc, wqkvc, b_qkv, qkv_buf, HID3);

    // 2) causal flash attention
    attn_kernel<<<dim3(SEQ / 128, NH, BATCH), 128, ATTN_SMEM>>>();

    // 3) out = attn @ Wdense^T + b
    split_kernel<<<(MROWS * HID / 4 + 255) / 256, 256>>>(attn_buf, attnc, MROWS);
    gemm_hmma_kernel<<<dim3(HID / 128, MROWS / 128), 256, GEMM_SMEM>>>(
        attnc, wdc, b_dense, out, HID);
}

// round 5
// speedup vs baseline: 2.6470x; 1.6782x over previous
#include <cuda_runtime.h>
#include <cuda_bf16.h>
#include <cstdint>
#include <math.h>

#define HID   2048
#define HID3  6144
#define NH    16
#define HD    128
#define BATCH 4
#define SEQ   2048
#define MROWS 8192
#define K2    4096          // storage: [hi | lo] bf16 per row
#define BKG   64            // bf16 k-chunk per stage (128B rows)
#define NCHT  96            // 3-term split: Ah*Bh + Al*Bh + Ah*Bl
#define GSTAGES 3
#define STG_BYTES 32768     // 16KB A + 16KB B per stage
#define GEMM_SMEM (GSTAGES*STG_BYTES)   // 98304

// ---------------- scratch (no allocations allowed) ----------------
__device__ float g_qkv[(size_t)MROWS * HID3];
__device__ float g_attn[(size_t)MROWS * HID];
__device__ __nv_bfloat16 g_xc[(size_t)MROWS * K2];
__device__ __nv_bfloat16 g_wqkvc[(size_t)HID3 * K2];
__device__ __nv_bfloat16 g_wdc[(size_t)HID * K2];
__device__ __nv_bfloat16 g_attnc[(size_t)MROWS * K2];
// attention operands: [bh][s][256] for Q,K ; [bh][256][s] for V^T (hi rows 0-127, lo 128-255)
__device__ __nv_bfloat16 g_qs[(size_t)BATCH * NH * SEQ * 256];
__device__ __nv_bfloat16 g_ks[(size_t)BATCH * NH * SEQ * 256];
__device__ __nv_bfloat16 g_vt[(size_t)BATCH * NH * 256 * SEQ];

// ---------------- helpers ----------------
__device__ __forceinline__ uint32_t s2u(const void* p) {
    uint32_t a;
    asm("{ .reg .u64 t; cvta.to.shared.u64 t, %1; cvt.u32.u64 %0, t; }"
        : "=r"(a) : "l"(p));
    return a;
}
__device__ __forceinline__ void cp16(uint32_t dst, const void* src) {
    asm volatile("cp.async.cg.shared.global [%0], [%1], 16;"
                 :: "r"(dst), "l"(src));
}
__device__ __forceinline__ void ldsm4(uint32_t* r, uint32_t addr) {
    asm volatile("ldmatrix.sync.aligned.m8n8.x4.shared.b16 {%0,%1,%2,%3}, [%4];"
        : "=r"(r[0]), "=r"(r[1]), "=r"(r[2]), "=r"(r[3]) : "r"(addr));
}
__device__ __forceinline__ void mma16816(float* c, const uint32_t* a,
                                         uint32_t b0, uint32_t b1) {
    asm volatile("mma.sync.aligned.m16n8k16.row.col.f32.bf16.bf16.f32 "
        "{%0,%1,%2,%3}, {%4,%5,%6,%7}, {%8,%9}, {%0,%1,%2,%3};"
        : "+f"(c[0]), "+f"(c[1]), "+f"(c[2]), "+f"(c[3])
        : "r"(a[0]), "r"(a[1]), "r"(a[2]), "r"(a[3]), "r"(b0), "r"(b1));
}
// pack two fp32 -> bf16x2 (lo = element0)
__device__ __forceinline__ uint32_t pkbf(float lo, float hi) {
    uint32_t r;
    asm("cvt.rn.bf16x2.f32 %0, %1, %2;" : "=r"(r) : "f"(hi), "f"(lo));
    return r;
}

// ---------------- split conversion: fp32[rows][2048] -> bf16[rows][hi|lo] ------
__global__ __launch_bounds__(256) void split_kernel(const float* __restrict__ in,
                                                    __nv_bfloat16* __restrict__ out,
                                                    int rows)
{
    size_t i = (size_t)blockIdx.x * 256 + threadIdx.x;
    size_t n4 = (size_t)rows * HID / 4;
    if (i >= n4) return;
    size_t e = i * 4;
    size_t r = e >> 11;
    int    c = (int)(e & 2047);
    float4 v = ((const float4*)in)[i];
    __nv_bfloat16 h0 = __float2bfloat16(v.x), h1 = __float2bfloat16(v.y);
    __nv_bfloat16 h2 = __float2bfloat16(v.z), h3 = __float2bfloat16(v.w);
    __nv_bfloat16 l0 = __float2bfloat16(v.x - __bfloat162float(h0));
    __nv_bfloat16 l1 = __float2bfloat16(v.y - __bfloat162float(h1));
    __nv_bfloat16 l2 = __float2bfloat16(v.z - __bfloat162float(h2));
    __nv_bfloat16 l3 = __float2bfloat16(v.w - __bfloat162float(h3));
    ushort4 hv = make_ushort4(__bfloat16_as_ushort(h0), __bfloat16_as_ushort(h1),
                              __bfloat16_as_ushort(h2), __bfloat16_as_ushort(h3));
    ushort4 lv = make_ushort4(__bfloat16_as_ushort(l0), __bfloat16_as_ushort(l1),
                              __bfloat16_as_ushort(l2), __bfloat16_as_ushort(l3));
    __nv_bfloat16* o = out + r * K2;
    *(ushort4*)(o + c)       = hv;
    *(ushort4*)(o + HID + c) = lv;
}

// ---------------- qkv split for attention ----------------
// reads g_qkv, writes g_qs (q*scale hi|lo), g_ks (hi|lo), g_vt (transposed hi;lo)
__global__ __launch_bounds__(256) void kvsplit_kernel()
{
    __shared__ __nv_bfloat16 vt[256][72];   // stride 72 to break bank alignment
    const int tid = threadIdx.x;
    const int blk = blockIdx.x, h = blockIdx.y, b = blockIdx.z;
    const int bh = b * NH + h;
    const int s0 = blk * 64;
    const float* base = g_qkv + (size_t)(b * SEQ + s0) * HID3 + h * HD;
    const float scale = 0.08838834764831845f;   // 1/sqrt(128)

#pragma unroll
    for (int i = 0; i < 8; i++) {
        int u = i * 256 + tid;          // 0..2047
        int r = u >> 5, c4 = (u & 31) * 4;
        size_t rowq = (size_t)bh * SEQ + s0 + r;
        // Q (scaled)
        float4 q = *(const float4*)(base + (size_t)r * HID3 + c4);
        q.x *= scale; q.y *= scale; q.z *= scale; q.w *= scale;
        {
            __nv_bfloat16 h0=__float2bfloat16(q.x),h1=__float2bfloat16(q.y),
                          h2=__float2bfloat16(q.z),h3=__float2bfloat16(q.w);
            __nv_bfloat16 l0=__float2bfloat16(q.x-__bfloat162float(h0)),
                          l1=__float2bfloat16(q.y-__bfloat162float(h1)),
                          l2=__float2bfloat16(q.z-__bfloat162float(h2)),
                          l3=__float2bfloat16(q.w-__bfloat162float(h3));
            *(ushort4*)(g_qs + rowq*256 + c4) =
                make_ushort4(__bfloat16_as_ushort(h0),__bfloat16_as_ushort(h1),
                             __bfloat16_as_ushort(h2),__bfloat16_as_ushort(h3));
            *(ushort4*)(g_qs + rowq*256 + 128 + c4) =
                make_ushort4(__bfloat16_as_ushort(l0),__bfloat16_as_ushort(l1),
                             __bfloat16_as_ushort(l2),__bfloat16_as_ushort(l3));
        }
        // K
        float4 k = *(const float4*)(base + HID + (size_t)r * HID3 + c4);
        {
            __nv_bfloat16 h0=__float2bfloat16(k.x),h1=__float2bfloat16(k.y),
                          h2=__float2bfloat16(k.z),h3=__float2bfloat16(k.w);
            __nv_bfloat16 l0=__float2bfloat16(k.x-__bfloat162float(h0)),
                          l1=__float2bfloat16(k.y-__bfloat162float(h1)),
                          l2=__float2bfloat16(k.z-__bfloat162float(h2)),
                          l3=__float2bfloat16(k.w-__bfloat162float(h3));
            *(ushort4*)(g_ks + rowq*256 + c4) =
                make_ushort4(__bfloat16_as_ushort(h0),__bfloat16_as_ushort(h1),
                             __bfloat16_as_ushort(h2),__bfloat16_as_ushort(h3));
            *(ushort4*)(g_ks + rowq*256 + 128 + c4) =
                make_ushort4(__bfloat16_as_ushort(l0),__bfloat16_as_ushort(l1),
                             __bfloat16_as_ushort(l2),__bfloat16_as_ushort(l3));
        }
        // V -> smem transpose (hi rows 0-127, lo rows 128-255)
        float4 v = *(const float4*)(base + 2 * HID + (size_t)r * HID3 + c4);
        float vv[4] = {v.x, v.y, v.z, v.w};
#pragma unroll
        for (int j = 0; j < 4; j++) {
            __nv_bfloat16 hb = __float2bfloat16(vv[j]);
            __nv_bfloat16 lb = __float2bfloat16(vv[j] - __bfloat162float(hb));
            vt[c4 + j][r]       = hb;
            vt[128 + c4 + j][r] = lb;
        }
    }
    __syncthreads();
#pragma unroll
    for (int i = 0; i < 16; i++) {
        int u = i * 256 + tid;          // 0..4095
        int r = u >> 4, c = (u & 15) * 4;
        ushort4 o = make_ushort4(__bfloat16_as_ushort(vt[r][c]),
                                 __bfloat16_as_ushort(vt[r][c+1]),
                                 __bfloat16_as_ushort(vt[r][c+2]),
                                 __bfloat16_as_ushort(vt[r][c+3]));
        *(ushort4*)(g_vt + ((size_t)bh * 256 + r) * SEQ + s0 + c) = o;
    }
}

// ---------------- HMMA GEMM (unchanged from R4) ----------------
__global__ __launch_bounds__(256, 2) void gemm_hmma_kernel(
    const __nv_bfloat16* __restrict__ A, const __nv_bfloat16* __restrict__ B,
    const float* __restrict__ bias, float* __restrict__ C, int Ncols)
{
    extern __shared__ char sm[];
    const uint32_t sb = s2u(sm);
    const int tid = threadIdx.x;
    const int wid = tid >> 5, lane = tid & 31;
    const size_t bm = (size_t)blockIdx.y * 128;
    const size_t bn = (size_t)blockIdx.x * 128;
    const int wm = wid & 3, wn = wid >> 2;

    auto issue = [&](int ch) {
        int ach = (ch < 64) ? ch : (ch - 64);
        int bch = (ch < 32) ? ch : (ch - 32);
        uint32_t st = sb + (ch % GSTAGES) * STG_BYTES;
        const __nv_bfloat16* Ab = A + (size_t)ach * BKG;
        const __nv_bfloat16* Bb = B + (size_t)bch * BKG;
#pragma unroll
        for (int i = 0; i < 4; i++) {
            int u = i * 256 + tid;
            int r = u >> 3, c = u & 7;
            uint32_t sw = (uint32_t)(r * 128) + (uint32_t)((c * 16) ^ ((r & 7) << 4));
            cp16(st + sw,         Ab + (bm + r) * K2 + c * 8);
            cp16(st + 16384 + sw, Bb + (bn + r) * K2 + c * 8);
        }
        asm volatile("cp.async.commit_group;");
    };

    issue(0);
    issue(1);

    float acc[2][8][4];
#pragma unroll
    for (int mi = 0; mi < 2; mi++)
#pragma unroll
        for (int ni = 0; ni < 8; ni++)
#pragma unroll
            for (int q = 0; q < 4; q++) acc[mi][ni][q] = 0.f;

    const int lm_row = lane & 15;
    const int lm_hi  = (lane >> 4) << 4;

    for (int ch = 0; ch < NCHT; ch++) {
        asm volatile("cp.async.wait_group 1;");
        __syncthreads();
        if (ch + 2 < NCHT) issue(ch + 2);
        uint32_t st = sb + (ch % GSTAGES) * STG_BYTES;
#pragma unroll
        for (int kk = 0; kk < 64; kk += 16) {
            uint32_t a[2][4];
#pragma unroll
            for (int mi = 0; mi < 2; mi++) {
                int row = wm * 32 + mi * 16 + lm_row;
                uint32_t byte = (uint32_t)(kk * 2 + lm_hi);
                ldsm4(a[mi], st + row * 128 + (byte ^ ((row & 7) << 4)));
            }
            uint32_t b[4][4];
#pragma unroll
            for (int g = 0; g < 4; g++) {
                int row = wn * 64 + g * 16 + lm_row;
                uint32_t byte = (uint32_t)(kk * 2 + lm_hi);
                ldsm4(b[g], st + 16384 + row * 128 + (byte ^ ((row & 7) << 4)));
            }
#pragma unroll
            for (int mi = 0; mi < 2; mi++)
#pragma unroll
                for (int ni = 0; ni < 8; ni++) {
                    int g = ni >> 1, h = ni & 1;
                    mma16816(acc[mi][ni], a[mi], b[g][h], b[g][h + 2]);
                }
        }
    }

    const int r0 = wm * 32 + (lane >> 2);
    const int c0 = wn * 64 + (lane & 3) * 2;
#pragma unroll
    for (int mi = 0; mi < 2; mi++)
#pragma unroll
        for (int ni = 0; ni < 8; ni++) {
            size_t col = bn + c0 + ni * 8;
            float2 bv = *(const float2*)(bias + col);
            float* p0 = C + (bm + r0 + mi * 16) * (size_t)Ncols + col;
            float* p1 = p0 + 8 * (size_t)Ncols;
            *(float2*)p0 = make_float2(acc[mi][ni][0] + bv.x, acc[mi][ni][1] + bv.y);
            *(float2*)p1 = make_float2(acc[mi][ni][2] + bv.x, acc[mi][ni][3] + bv.y);
        }
}

// ---------------- HMMA causal flash attention ----------------
// grid (16, NH, BATCH) with qb reversed; 256 threads = 8 warps x m16 rows.
// SMEM: Qs 128x512B (64KB) + 2 stages x (K 64x512B + Vt 256x128B) (64KB each).
#define ATTN_SMEM 196608
__global__ __launch_bounds__(256, 1) void attn_hmma_kernel()
{
    extern __shared__ char smc[];
    const uint32_t sb = s2u(smc);
    const int tid = threadIdx.x, w = tid >> 5, lane = tid & 31;
    const int qb = 15 - blockIdx.x, h = blockIdx.y, b = blockIdx.z;
    const int bh = b * NH + h;
    const int nkb = (qb + 1) * 2;
    const int lm_row = lane & 15;
    const int lm_hi  = (lane >> 4) << 4;

    // ---- issue Q + KV(0) (group), KV(1) (group) ----
    {
        const __nv_bfloat16* Qg = g_qs + ((size_t)bh * SEQ + qb * 128) * 256;
#pragma unroll
        for (int i = 0; i < 16; i++) {
            int u = i * 256 + tid;
            int r = u >> 5, c = u & 31;
            cp16(sb + r * 512 + ((c * 16) ^ ((r & 7) << 4)), Qg + (size_t)r * 256 + c * 8);
        }
    }
    auto issue_kv = [&](int kb) {
        uint32_t kst = sb + 65536 + (kb & 1) * 65536;
#pragma unroll
        for (int i = 0; i < 8; i++) {
            int u = i * 256 + tid;
            int r = u >> 5, c = u & 31;
            cp16(kst + r * 512 + ((c * 16) ^ ((r & 7) << 4)),
                 g_ks + ((size_t)bh * SEQ + kb * 64 + r) * 256 + c * 8);
        }
#pragma unroll
        for (int i = 0; i < 8; i++) {
            int u = i * 256 + tid;
            int r = u >> 3, c = u & 7;
            cp16(kst + 32768 + r * 128 + ((c * 16) ^ ((r & 7) << 4)),
                 g_vt + ((size_t)bh * 256 + r) * SEQ + kb * 64 + c * 8);
        }
        asm volatile("cp.async.commit_group;");
    };
    issue_kv(0);
    if (nkb > 1) issue_kv(1);

    float oacc[16][4];
#pragma unroll
    for (int g = 0; g < 16; g++)
#pragma unroll
        for (int e = 0; e < 4; e++) oacc[g][e] = 0.f;
    float m0 = -1e30f, m1 = -1e30f, lp0 = 0.f, lp1 = 0.f;

    const int row0 = qb * 128 + w * 16 + (lane >> 2);   // this lane's first row
    const int wrow_max = qb * 128 + w * 16 + 15;

    for (int kb = 0; kb < nkb; kb++) {
        if (kb + 1 < nkb) asm volatile("cp.async.wait_group 1;");
        else              asm volatile("cp.async.wait_group 0;");
        __syncthreads();

        const bool active = (kb * 64) <= wrow_max;
        if (active) {
            const uint32_t kst = sb + 65536 + (kb & 1) * 65536;
            const uint32_t vst = kst + 32768;

            // ---- S = Qh*Kh + Ql*Kh + Qh*Kl ----
            float sacc[8][4];
#pragma unroll
            for (int j = 0; j < 8; j++)
#pragma unroll
                for (int e = 0; e < 4; e++) sacc[j][e] = 0.f;

#pragma unroll
            for (int kk = 0; kk < 8; kk++) {
                const int qrow = w * 16 + lm_row;
                uint32_t qa = sb + qrow * 512 +
                              ((uint32_t)(kk * 32 + lm_hi) ^ ((qrow & 7) << 4));
                uint32_t ah[4], al[4];
                ldsm4(ah, qa);
                ldsm4(al, qa + 256);
#pragma unroll
                for (int g = 0; g < 4; g++) {
                    const int krow = g * 16 + lm_row;
                    uint32_t ka = kst + krow * 512 +
                                  ((uint32_t)(kk * 32 + lm_hi) ^ ((krow & 7) << 4));
                    uint32_t bhh[4], bll[4];
                    ldsm4(bhh, ka);
                    ldsm4(bll, ka + 256);
                    mma16816(sacc[2*g],   ah, bhh[0], bhh[2]);
                    mma16816(sacc[2*g+1], ah, bhh[1], bhh[3]);
                    mma16816(sacc[2*g],   al, bhh[0], bhh[2]);
                    mma16816(sacc[2*g+1], al, bhh[1], bhh[3]);
                    mma16816(sacc[2*g],   ah, bll[0], bll[2]);
                    mma16816(sacc[2*g+1], ah, bll[1], bll[3]);
                }
            }

            // ---- mask + online softmax ----
            float mx0 = -1e30f, mx1 = -1e30f;
#pragma unroll
            for (int j = 0; j < 8; j++) {
                int colb = kb * 64 + j * 8 + (lane & 3) * 2;
                if (colb     > row0)     sacc[j][0] = -1e30f;
                if (colb + 1 > row0)     sacc[j][1] = -1e30f;
                if (colb     > row0 + 8) sacc[j][2] = -1e30f;
                if (colb + 1 > row0 + 8) sacc[j][3] = -1e30f;
                mx0 = fmaxf(mx0, fmaxf(sacc[j][0], sacc[j][1]));
                mx1 = fmaxf(mx1, fmaxf(sacc[j][2], sacc[j][3]));
            }
            mx0 = fmaxf(mx0, __shfl_xor_sync(0xffffffffu, mx0, 1));
            mx0 = fmaxf(mx0, __shfl_xor_sync(0xffffffffu, mx0, 2));
            mx1 = fmaxf(mx1, __shfl_xor_sync(0xffffffffu, mx1, 1));
            mx1 = fmaxf(mx1, __shfl_xor_sync(0xffffffffu, mx1, 2));
            float mn0 = fmaxf(m0, mx0), mn1 = fmaxf(m1, mx1);
            float al0 = __expf(m0 - mn0), al1 = __expf(m1 - mn1);
            m0 = mn0; m1 = mn1;
            float s0 = 0.f, s1 = 0.f;
#pragma unroll
            for (int j = 0; j < 8; j++) {
                sacc[j][0] = __expf(sacc[j][0] - mn0); s0 += sacc[j][0];
                sacc[j][1] = __expf(sacc[j][1] - mn0); s0 += sacc[j][1];
                sacc[j][2] = __expf(sacc[j][2] - mn1); s1 += sacc[j][2];
                sacc[j][3] = __expf(sacc[j][3] - mn1); s1 += sacc[j][3];
            }
            lp0 = lp0 * al0 + s0;
            lp1 = lp1 * al1 + s1;
#pragma unroll
            for (int g = 0; g < 16; g++) {
                oacc[g][0] *= al0; oacc[g][1] *= al0;
                oacc[g][2] *= al1; oacc[g][3] *= al1;
            }

            // ---- O += (Ph+Pl) * Vh + Ph * Vl ----
#pragma unroll
            for (int t = 0; t < 4; t++) {
                const int f0 = 2 * t, f1 = 2 * t + 1;
                float ph[8], pl[8];
#pragma unroll
                for (int e = 0; e < 4; e++) {
                    float p0v = sacc[f0][e], p1v = sacc[f1][e];
                    float h0f = __bfloat162float(__float2bfloat16(p0v));
                    float h1f = __bfloat162float(__float2bfloat16(p1v));
                    ph[e]     = h0f; pl[e]     = p0v - h0f;
                    ph[4 + e] = h1f; pl[4 + e] = p1v - h1f;
                }
                uint32_t aPh[4], aPl[4];
                aPh[0] = pkbf(ph[0], ph[1]); aPh[1] = pkbf(ph[2], ph[3]);
                aPh[2] = pkbf(ph[4], ph[5]); aPh[3] = pkbf(ph[6], ph[7]);
                aPl[0] = pkbf(pl[0], pl[1]); aPl[1] = pkbf(pl[2], pl[3]);
                aPl[2] = pkbf(pl[4], pl[5]); aPl[3] = pkbf(pl[6], pl[7]);
#pragma unroll
                for (int g = 0; g < 8; g++) {
                    const int vrow = g * 16 + lm_row;
                    uint32_t va = vst + vrow * 128 +
                                  ((uint32_t)(t * 32 + lm_hi) ^ ((vrow & 7) << 4));
                    uint32_t bhh[4], bll[4];
                    ldsm4(bhh, va);
                    ldsm4(bll, va + 16384);     // lo rows at +128*128B
                    mma16816(oacc[2*g],   aPh, bhh[0], bhh[2]);
                    mma16816(oacc[2*g+1], aPh, bhh[1], bhh[3]);
                    mma16816(oacc[2*g],   aPl, bhh[0], bhh[2]);
                    mma16816(oacc[2*g+1], aPl, bhh[1], bhh[3]);
                    mma16816(oacc[2*g],   aPh, bll[0], bll[2]);
                    mma16816(oacc[2*g+1], aPh, bll[1], bll[3]);
                }
            }
        }
        __syncthreads();
        if (kb + 2 < nkb) issue_kv(kb + 2);
    }

    // ---- finalize ----
    lp0 += __shfl_xor_sync(0xffffffffu, lp0, 1);
    lp0 += __shfl_xor_sync(0xffffffffu, lp0, 2);
    lp1 += __shfl_xor_sync(0xffffffffu, lp1, 1);
    lp1 += __shfl_xor_sync(0xffffffffu, lp1, 2);
    const float inv0 = 1.f / lp0, inv1 = 1.f / lp1;

    const size_t gr = (size_t)b * SEQ + qb * 128 + w * 16 + (lane >> 2);
    const int colb = h * 128 + (lane & 3) * 2;
#pragma unroll
    for (int g = 0; g < 16; g++) {
        float* p0 = g_attn + gr * HID + colb + g * 8;
        float* p1 = p0 + 8 * HID;
        *(float2*)p0 = make_float2(oacc[g][0] * inv0, oacc[g][1] * inv0);
        *(float2*)p1 = make_float2(oacc[g][2] * inv1, oacc[g][3] * inv1);
    }
}

// ---------------- launch ----------------
extern "C" void kernel_launch(void* const* d_in, const int* in_sizes, int n_in,
                              void* d_out, int out_size)
{
    (void)in_sizes; (void)n_in; (void)out_size;
    const float* x       = (const float*)d_in[0];
    const float* w_qkv   = (const float*)d_in[1];
    const float* b_qkv   = (const float*)d_in[2];
    const float* w_dense = (const float*)d_in[3];
    const float* b_dense = (const float*)d_in[4];
    float* out = (float*)d_out;

    float *qkv_buf, *attn_buf;
    __nv_bfloat16 *xc, *wqkvc, *wdc, *attnc;
    cudaGetSymbolAddress((void**)&qkv_buf, g_qkv);
    cudaGetSymbolAddress((void**)&attn_buf, g_attn);
    cudaGetSymbolAddress((void**)&xc, g_xc);
    cudaGetSymbolAddress((void**)&wqkvc, g_wqkvc);
    cudaGetSymbolAddress((void**)&wdc, g_wdc);
    cudaGetSymbolAddress((void**)&attnc, g_attnc);

    cudaFuncSetAttribute(gemm_hmma_kernel,
                         cudaFuncAttributeMaxDynamicSharedMemorySize, GEMM_SMEM);
    cudaFuncSetAttribute(attn_hmma_kernel,
                         cudaFuncAttributeMaxDynamicSharedMemorySize, ATTN_SMEM);

    // split conversions (fp32 -> bf16 hi|lo)
    split_kernel<<<(MROWS * HID / 4 + 255) / 256, 256>>>(x, xc, MROWS);
    split_kernel<<<(HID3 * HID / 4 + 255) / 256, 256>>>(w_qkv, wqkvc, HID3);
    split_kernel<<<(HID  * HID / 4 + 255) / 256, 256>>>(w_dense, wdc, HID);

    // 1) QKV = X @ Wqkv^T + b
    gemm_hmma_kernel<<<dim3(HID3 / 128, MROWS / 128), 256, GEMM_SMEM>>>(
        xc, wqkvc, b_qkv, qkv_buf, HID3);

    // 2) attention operand prep + HMMA flash attention
    kvsplit_kernel<<<dim3(SEQ / 64, NH, BATCH), 256>>>();
    attn_hmma_kernel<<<dim3(16, NH, BATCH), 256, ATTN_SMEM>>>();

    // 3) out = attn @ Wdense^T + b
    split_kernel<<<(MROWS * HID / 4 + 255) / 256, 256>>>(attn_buf, attnc, MROWS);
    gemm_hmma_kernel<<<dim3(HID / 128, MROWS / 128), 256, GEMM_SMEM>>>(
        attnc, wdc, b_dense, out, HID);
}

// round 6
// speedup vs baseline: 2.6568x; 1.0037x over previous
#include <cuda_runtime.h>
#include <cuda_bf16.h>
#include <cstdint>
#include <math.h>

#define HID   2048
#define HID3  6144
#define NH    16
#define HD    128
#define BATCH 4
#define SEQ   2048
#define MROWS 8192
#define K2    4096          // storage: [hi | lo] bf16 per row
#define BKG   64            // bf16 k-chunk per stage (128B rows)
#define NCHT  96            // 3-term split: Ah*Bh + Al*Bh + Ah*Bl
#define GSTAGES 3
#define STG_BYTES 32768     // 16KB A + 16KB B per stage
#define GEMM_SMEM (GSTAGES*STG_BYTES)   // 98304

// ---------------- scratch (no allocations allowed) ----------------
__device__ __nv_bfloat16 g_xc[(size_t)MROWS * K2];
__device__ __nv_bfloat16 g_wqkvc[(size_t)HID3 * K2];
__device__ __nv_bfloat16 g_wdc[(size_t)HID * K2];
__device__ __nv_bfloat16 g_attnc[(size_t)MROWS * K2];
// attention operands: [bh][s][256] for Q,K ; [bh][256][s] for V^T (hi rows 0-127, lo 128-255)
__device__ __nv_bfloat16 g_qs[(size_t)BATCH * NH * SEQ * 256];
__device__ __nv_bfloat16 g_ks[(size_t)BATCH * NH * SEQ * 256];
__device__ __nv_bfloat16 g_vt[(size_t)BATCH * NH * 256 * SEQ];

// ---------------- helpers ----------------
__device__ __forceinline__ uint32_t s2u(const void* p) {
    uint32_t a;
    asm("{ .reg .u64 t; cvta.to.shared.u64 t, %1; cvt.u32.u64 %0, t; }"
        : "=r"(a) : "l"(p));
    return a;
}
__device__ __forceinline__ void cp16(uint32_t dst, const void* src) {
    asm volatile("cp.async.cg.shared.global [%0], [%1], 16;"
                 :: "r"(dst), "l"(src));
}
__device__ __forceinline__ void ldsm4(uint32_t* r, uint32_t addr) {
    asm volatile("ldmatrix.sync.aligned.m8n8.x4.shared.b16 {%0,%1,%2,%3}, [%4];"
        : "=r"(r[0]), "=r"(r[1]), "=r"(r[2]), "=r"(r[3]) : "r"(addr));
}
__device__ __forceinline__ void mma16816(float* c, const uint32_t* a,
                                         uint32_t b0, uint32_t b1) {
    asm volatile("mma.sync.aligned.m16n8k16.row.col.f32.bf16.bf16.f32 "
        "{%0,%1,%2,%3}, {%4,%5,%6,%7}, {%8,%9}, {%0,%1,%2,%3};"
        : "+f"(c[0]), "+f"(c[1]), "+f"(c[2]), "+f"(c[3])
        : "r"(a[0]), "r"(a[1]), "r"(a[2]), "r"(a[3]), "r"(b0), "r"(b1));
}
__device__ __forceinline__ uint32_t pkbf(float lo, float hi) {
    uint32_t r;
    asm("cvt.rn.bf16x2.f32 %0, %1, %2;" : "=r"(r) : "f"(hi), "f"(lo));
    return r;
}
__device__ __forceinline__ void split1(float v, unsigned short& h, unsigned short& l) {
    __nv_bfloat16 hb = __float2bfloat16(v);
    __nv_bfloat16 lb = __float2bfloat16(v - __bfloat162float(hb));
    h = __bfloat16_as_ushort(hb);
    l = __bfloat16_as_ushort(lb);
}

// ---------------- split conversion: fp32[rows][2048] -> bf16[rows][hi|lo] ------
__global__ __launch_bounds__(256) void split_kernel(const float* __restrict__ in,
                                                    __nv_bfloat16* __restrict__ out,
                                                    int rows)
{
    size_t i = (size_t)blockIdx.x * 256 + threadIdx.x;
    size_t n4 = (size_t)rows * HID / 4;
    if (i >= n4) return;
    size_t e = i * 4;
    size_t r = e >> 11;
    int    c = (int)(e & 2047);
    float4 v = ((const float4*)in)[i];
    unsigned short h0,h1,h2,h3,l0,l1,l2,l3;
    split1(v.x,h0,l0); split1(v.y,h1,l1); split1(v.z,h2,l2); split1(v.w,h3,l3);
    __nv_bfloat16* o = out + r * K2;
    *(ushort4*)(o + c)       = make_ushort4(h0,h1,h2,h3);
    *(ushort4*)(o + HID + c) = make_ushort4(l0,l1,l2,l3);
}

// ---------------- QKV GEMM with fused operand epilogue ----------------
// C tile (128x128) = one head's slice of Q, K, or V; writes g_qs/g_ks/g_vt directly.
__global__ __launch_bounds__(256, 2) void gemm_qkv_kernel(
    const __nv_bfloat16* __restrict__ A, const __nv_bfloat16* __restrict__ B,
    const float* __restrict__ bias)
{
    extern __shared__ char sm[];
    const uint32_t sb = s2u(sm);
    const int tid = threadIdx.x;
    const int wid = tid >> 5, lane = tid & 31;
    const size_t bm = (size_t)blockIdx.y * 128;
    const size_t bn = (size_t)blockIdx.x * 128;
    const int wm = wid & 3, wn = wid >> 2;

    auto issue = [&](int ch) {
        int ach = (ch < 64) ? ch : (ch - 64);
        int bch = (ch < 32) ? ch : (ch - 32);
        uint32_t st = sb + (ch % GSTAGES) * STG_BYTES;
        const __nv_bfloat16* Ab = A + (size_t)ach * BKG;
        const __nv_bfloat16* Bb = B + (size_t)bch * BKG;
#pragma unroll
        for (int i = 0; i < 4; i++) {
            int u = i * 256 + tid;
            int r = u >> 3, c = u & 7;
            uint32_t sw = (uint32_t)(r * 128) + (uint32_t)((c * 16) ^ ((r & 7) << 4));
            cp16(st + sw,         Ab + (bm + r) * K2 + c * 8);
            cp16(st + 16384 + sw, Bb + (bn + r) * K2 + c * 8);
        }
        asm volatile("cp.async.commit_group;");
    };

    issue(0);
    issue(1);

    float acc[2][8][4];
#pragma unroll
    for (int mi = 0; mi < 2; mi++)
#pragma unroll
        for (int ni = 0; ni < 8; ni++)
#pragma unroll
            for (int q = 0; q < 4; q++) acc[mi][ni][q] = 0.f;

    const int lm_row = lane & 15;
    const int lm_hi  = (lane >> 4) << 4;

    for (int ch = 0; ch < NCHT; ch++) {
        asm volatile("cp.async.wait_group 1;");
        __syncthreads();
        if (ch + 2 < NCHT) issue(ch + 2);
        uint32_t st = sb + (ch % GSTAGES) * STG_BYTES;
#pragma unroll
        for (int kk = 0; kk < 64; kk += 16) {
            uint32_t a[2][4];
#pragma unroll
            for (int mi = 0; mi < 2; mi++) {
                int row = wm * 32 + mi * 16 + lm_row;
                uint32_t byte = (uint32_t)(kk * 2 + lm_hi);
                ldsm4(a[mi], st + row * 128 + (byte ^ ((row & 7) << 4)));
            }
            uint32_t b[4][4];
#pragma unroll
            for (int g = 0; g < 4; g++) {
                int row = wn * 64 + g * 16 + lm_row;
                uint32_t byte = (uint32_t)(kk * 2 + lm_hi);
                ldsm4(b[g], st + 16384 + row * 128 + (byte ^ ((row & 7) << 4)));
            }
#pragma unroll
            for (int mi = 0; mi < 2; mi++)
#pragma unroll
                for (int ni = 0; ni < 8; ni++) {
                    int g = ni >> 1, h = ni & 1;
                    mma16816(acc[mi][ni], a[mi], b[g][h], b[g][h + 2]);
                }
        }
    }

    // ---- fused epilogue ----
    const int r0 = wm * 32 + (lane >> 2);
    const int c0 = wn * 64 + (lane & 3) * 2;
    const int sec = (int)(bn >> 11);            // 0=Q 1=K 2=V
    const int hh  = ((int)bn & 2047) >> 7;
    const int b_  = (int)(bm >> 11);
    const int s_base = (int)bm & 2047;
    const size_t bh = (size_t)b_ * NH + hh;
    const float qscale = 0.08838834764831845f;

    if (sec < 2) {
        __nv_bfloat16* dst = (sec == 0) ? g_qs : g_ks;
        const float sc = (sec == 0) ? qscale : 1.f;
#pragma unroll
        for (int mi = 0; mi < 2; mi++)
#pragma unroll
            for (int ni = 0; ni < 8; ni++) {
                int d = c0 + ni * 8;
                float2 bv = *(const float2*)(bias + bn + d);
                float o0 = (acc[mi][ni][0] + bv.x) * sc;
                float o1 = (acc[mi][ni][1] + bv.y) * sc;
                float o2 = (acc[mi][ni][2] + bv.x) * sc;
                float o3 = (acc[mi][ni][3] + bv.y) * sc;
                unsigned short h0,h1,h2,h3,l0,l1,l2,l3;
                split1(o0,h0,l0); split1(o1,h1,l1);
                split1(o2,h2,l2); split1(o3,h3,l3);
                int ra = s_base + r0 + mi * 16;
                __nv_bfloat16* pa = dst + (bh * SEQ + ra) * 256 + d;
                *(ushort2*)pa         = make_ushort2(h0,h1);
                *(ushort2*)(pa + 128) = make_ushort2(l0,l1);
                __nv_bfloat16* pb = pa + 8 * 256;
                *(ushort2*)pb         = make_ushort2(h2,h3);
                *(ushort2*)(pb + 128) = make_ushort2(l2,l3);
            }
    } else {
        // V: transpose through smem, then split to g_vt[bh][d(hi)/(128+d)(lo)][s]
        __syncthreads();
        float* smT = (float*)sm;                 // [128 cols][129]
#pragma unroll
        for (int mi = 0; mi < 2; mi++)
#pragma unroll
            for (int ni = 0; ni < 8; ni++) {
                int d = c0 + ni * 8;
                float2 bv = *(const float2*)(bias + bn + d);
                int ra = r0 + mi * 16;
                smT[d * 129 + ra]           = acc[mi][ni][0] + bv.x;
                smT[(d + 1) * 129 + ra]     = acc[mi][ni][1] + bv.y;
                smT[d * 129 + ra + 8]       = acc[mi][ni][2] + bv.x;
                smT[(d + 1) * 129 + ra + 8] = acc[mi][ni][3] + bv.y;
            }
        __syncthreads();
        const int d = tid >> 1;
        const int sOff = (tid & 1) * 64;
        __nv_bfloat16* ph = g_vt + (bh * 256 + d) * SEQ + s_base + sOff;
        __nv_bfloat16* pl = ph + (size_t)128 * SEQ;
#pragma unroll
        for (int i = 0; i < 16; i++) {
            int s = i * 4;
            float v0 = smT[d * 129 + sOff + s + 0];
            float v1 = smT[d * 129 + sOff + s + 1];
            float v2 = smT[d * 129 + sOff + s + 2];
            float v3 = smT[d * 129 + sOff + s + 3];
            unsigned short h0,h1,h2,h3,l0,l1,l2,l3;
            split1(v0,h0,l0); split1(v1,h1,l1);
            split1(v2,h2,l2); split1(v3,h3,l3);
            *(ushort4*)(ph + s) = make_ushort4(h0,h1,h2,h3);
            *(ushort4*)(pl + s) = make_ushort4(l0,l1,l2,l3);
        }
    }
}

// ---------------- generic HMMA GEMM (dense layer) ----------------
__global__ __launch_bounds__(256, 2) void gemm_hmma_kernel(
    const __nv_bfloat16* __restrict__ A, const __nv_bfloat16* __restrict__ B,
    const float* __restrict__ bias, float* __restrict__ C, int Ncols)
{
    extern __shared__ char sm[];
    const uint32_t sb = s2u(sm);
    const int tid = threadIdx.x;
    const int wid = tid >> 5, lane = tid & 31;
    const size_t bm = (size_t)blockIdx.y * 128;
    const size_t bn = (size_t)blockIdx.x * 128;
    const int wm = wid & 3, wn = wid >> 2;

    auto issue = [&](int ch) {
        int ach = (ch < 64) ? ch : (ch - 64);
        int bch = (ch < 32) ? ch : (ch - 32);
        uint32_t st = sb + (ch % GSTAGES) * STG_BYTES;
        const __nv_bfloat16* Ab = A + (size_t)ach * BKG;
        const __nv_bfloat16* Bb = B + (size_t)bch * BKG;
#pragma unroll
        for (int i = 0; i < 4; i++) {
            int u = i * 256 + tid;
            int r = u >> 3, c = u & 7;
            uint32_t sw = (uint32_t)(r * 128) + (uint32_t)((c * 16) ^ ((r & 7) << 4));
            cp16(st + sw,         Ab + (bm + r) * K2 + c * 8);
            cp16(st + 16384 + sw, Bb + (bn + r) * K2 + c * 8);
        }
        asm volatile("cp.async.commit_group;");
    };

    issue(0);
    issue(1);

    float acc[2][8][4];
#pragma unroll
    for (int mi = 0; mi < 2; mi++)
#pragma unroll
        for (int ni = 0; ni < 8; ni++)
#pragma unroll
            for (int q = 0; q < 4; q++) acc[mi][ni][q] = 0.f;

    const int lm_row = lane & 15;
    const int lm_hi  = (lane >> 4) << 4;

    for (int ch = 0; ch < NCHT; ch++) {
        asm volatile("cp.async.wait_group 1;");
        __syncthreads();
        if (ch + 2 < NCHT) issue(ch + 2);
        uint32_t st = sb + (ch % GSTAGES) * STG_BYTES;
#pragma unroll
        for (int kk = 0; kk < 64; kk += 16) {
            uint32_t a[2][4];
#pragma unroll
            for (int mi = 0; mi < 2; mi++) {
                int row = wm * 32 + mi * 16 + lm_row;
                uint32_t byte = (uint32_t)(kk * 2 + lm_hi);
                ldsm4(a[mi], st + row * 128 + (byte ^ ((row & 7) << 4)));
            }
            uint32_t b[4][4];
#pragma unroll
            for (int g = 0; g < 4; g++) {
                int row = wn * 64 + g * 16 + lm_row;
                uint32_t byte = (uint32_t)(kk * 2 + lm_hi);
                ldsm4(b[g], st + 16384 + row * 128 + (byte ^ ((row & 7) << 4)));
            }
#pragma unroll
            for (int mi = 0; mi < 2; mi++)
#pragma unroll
                for (int ni = 0; ni < 8; ni++) {
                    int g = ni >> 1, h = ni & 1;
                    mma16816(acc[mi][ni], a[mi], b[g][h], b[g][h + 2]);
                }
        }
    }

    const int r0 = wm * 32 + (lane >> 2);
    const int c0 = wn * 64 + (lane & 3) * 2;
#pragma unroll
    for (int mi = 0; mi < 2; mi++)
#pragma unroll
        for (int ni = 0; ni < 8; ni++) {
            size_t col = bn + c0 + ni * 8;
            float2 bv = *(const float2*)(bias + col);
            float* p0 = C + (bm + r0 + mi * 16) * (size_t)Ncols + col;
            float* p1 = p0 + 8 * (size_t)Ncols;
            *(float2*)p0 = make_float2(acc[mi][ni][0] + bv.x, acc[mi][ni][1] + bv.y);
            *(float2*)p1 = make_float2(acc[mi][ni][2] + bv.x, acc[mi][ni][3] + bv.y);
        }
}

// ---------------- HMMA causal flash attention ----------------
// grid (16, NH, BATCH) with qb reversed; 256 threads = 8 warps x m16 rows.
#define ATTN_SMEM 196608
__global__ __launch_bounds__(256, 1) void attn_hmma_kernel()
{
    extern __shared__ char smc[];
    const uint32_t sb = s2u(smc);
    const int tid = threadIdx.x, w = tid >> 5, lane = tid & 31;
    const int qb = 15 - blockIdx.x, h = blockIdx.y, b = blockIdx.z;
    const int bh = b * NH + h;
    const int nkb = (qb + 1) * 2;
    const int lm_row = lane & 15;
    const int lm_hi  = (lane >> 4) << 4;

    {
        const __nv_bfloat16* Qg = g_qs + ((size_t)bh * SEQ + qb * 128) * 256;
#pragma unroll
        for (int i = 0; i < 16; i++) {
            int u = i * 256 + tid;
            int r = u >> 5, c = u & 31;
            cp16(sb + r * 512 + ((c * 16) ^ ((r & 7) << 4)), Qg + (size_t)r * 256 + c * 8);
        }
    }
    auto issue_kv = [&](int kb) {
        uint32_t kst = sb + 65536 + (kb & 1) * 65536;
#pragma unroll
        for (int i = 0; i < 8; i++) {
            int u = i * 256 + tid;
            int r = u >> 5, c = u & 31;
            cp16(kst + r * 512 + ((c * 16) ^ ((r & 7) << 4)),
                 g_ks + ((size_t)bh * SEQ + kb * 64 + r) * 256 + c * 8);
        }
#pragma unroll
        for (int i = 0; i < 8; i++) {
            int u = i * 256 + tid;
            int r = u >> 3, c = u & 7;
            cp16(kst + 32768 + r * 128 + ((c * 16) ^ ((r & 7) << 4)),
                 g_vt + ((size_t)bh * 256 + r) * SEQ + kb * 64 + c * 8);
        }
        asm volatile("cp.async.commit_group;");
    };
    issue_kv(0);
    if (nkb > 1) issue_kv(1);

    float oacc[16][4];
#pragma unroll
    for (int g = 0; g < 16; g++)
#pragma unroll
        for (int e = 0; e < 4; e++) oacc[g][e] = 0.f;
    float m0 = -1e30f, m1 = -1e30f, lp0 = 0.f, lp1 = 0.f;

    const int row0 = qb * 128 + w * 16 + (lane >> 2);
    const int wrow_max = qb * 128 + w * 16 + 15;

    for (int kb = 0; kb < nkb; kb++) {
        if (kb + 1 < nkb) asm volatile("cp.async.wait_group 1;");
        else              asm volatile("cp.async.wait_group 0;");
        __syncthreads();

        const bool active = (kb * 64) <= wrow_max;
        if (active) {
            const uint32_t kst = sb + 65536 + (kb & 1) * 65536;
            const uint32_t vst = kst + 32768;

            float sacc[8][4];
#pragma unroll
            for (int j = 0; j < 8; j++)
#pragma unroll
                for (int e = 0; e < 4; e++) sacc[j][e] = 0.f;

#pragma unroll
            for (int kk = 0; kk < 8; kk++) {
                const int qrow = w * 16 + lm_row;
                uint32_t qa = sb + qrow * 512 +
                              ((uint32_t)(kk * 32 + lm_hi) ^ ((qrow & 7) << 4));
                uint32_t ah[4], al[4];
                ldsm4(ah, qa);
                ldsm4(al, qa + 256);
#pragma unroll
                for (int g = 0; g < 4; g++) {
                    const int krow = g * 16 + lm_row;
                    uint32_t ka = kst + krow * 512 +
                                  ((uint32_t)(kk * 32 + lm_hi) ^ ((krow & 7) << 4));
                    uint32_t bhh[4], bll[4];
                    ldsm4(bhh, ka);
                    ldsm4(bll, ka + 256);
                    mma16816(sacc[2*g],   ah, bhh[0], bhh[2]);
                    mma16816(sacc[2*g+1], ah, bhh[1], bhh[3]);
                    mma16816(sacc[2*g],   al, bhh[0], bhh[2]);
                    mma16816(sacc[2*g+1], al, bhh[1], bhh[3]);
                    mma16816(sacc[2*g],   ah, bll[0], bll[2]);
                    mma16816(sacc[2*g+1], ah, bll[1], bll[3]);
                }
            }

            float mx0 = -1e30f, mx1 = -1e30f;
#pragma unroll
            for (int j = 0; j < 8; j++) {
                int colb = kb * 64 + j * 8 + (lane & 3) * 2;
                if (colb     > row0)     sacc[j][0] = -1e30f;
                if (colb + 1 > row0)     sacc[j][1] = -1e30f;
                if (colb     > row0 + 8) sacc[j][2] = -1e30f;
                if (colb + 1 > row0 + 8) sacc[j][3] = -1e30f;
                mx0 = fmaxf(mx0, fmaxf(sacc[j][0], sacc[j][1]));
                mx1 = fmaxf(mx1, fmaxf(sacc[j][2], sacc[j][3]));
            }
            mx0 = fmaxf(mx0, __shfl_xor_sync(0xffffffffu, mx0, 1));
            mx0 = fmaxf(mx0, __shfl_xor_sync(0xffffffffu, mx0, 2));
            mx1 = fmaxf(mx1, __shfl_xor_sync(0xffffffffu, mx1, 1));
            mx1 = fmaxf(mx1, __shfl_xor_sync(0xffffffffu, mx1, 2));
            float mn0 = fmaxf(m0, mx0), mn1 = fmaxf(m1, mx1);
            float al0 = __expf(m0 - mn0), al1 = __expf(m1 - mn1);
            m0 = mn0; m1 = mn1;
            float s0 = 0.f, s1 = 0.f;
#pragma unroll
            for (int j = 0; j < 8; j++) {
                sacc[j][0] = __expf(sacc[j][0] - mn0); s0 += sacc[j][0];
                sacc[j][1] = __expf(sacc[j][1] - mn0); s0 += sacc[j][1];
                sacc[j][2] = __expf(sacc[j][2] - mn1); s1 += sacc[j][2];
                sacc[j][3] = __expf(sacc[j][3] - mn1); s1 += sacc[j][3];
            }
            lp0 = lp0 * al0 + s0;
            lp1 = lp1 * al1 + s1;
#pragma unroll
            for (int g = 0; g < 16; g++) {
                oacc[g][0] *= al0; oacc[g][1] *= al0;
                oacc[g][2] *= al1; oacc[g][3] *= al1;
            }

#pragma unroll
            for (int t = 0; t < 4; t++) {
                const int f0 = 2 * t, f1 = 2 * t + 1;
                float ph[8], pl[8];
#pragma unroll
                for (int e = 0; e < 4; e++) {
                    float p0v = sacc[f0][e], p1v = sacc[f1][e];
                    float h0f = __bfloat162float(__float2bfloat16(p0v));
                    float h1f = __bfloat162float(__float2bfloat16(p1v));
                    ph[e]     = h0f; pl[e]     = p0v - h0f;
                    ph[4 + e] = h1f; pl[4 + e] = p1v - h1f;
                }
                uint32_t aPh[4], aPl[4];
                aPh[0] = pkbf(ph[0], ph[1]); aPh[1] = pkbf(ph[2], ph[3]);
                aPh[2] = pkbf(ph[4], ph[5]); aPh[3] = pkbf(ph[6], ph[7]);
                aPl[0] = pkbf(pl[0], pl[1]); aPl[1] = pkbf(pl[2], pl[3]);
                aPl[2] = pkbf(pl[4], pl[5]); aPl[3] = pkbf(pl[6], pl[7]);
#pragma unroll
                for (int g = 0; g < 8; g++) {
                    const int vrow = g * 16 + lm_row;
                    uint32_t va = vst + vrow * 128 +
                                  ((uint32_t)(t * 32 + lm_hi) ^ ((vrow & 7) << 4));
                    uint32_t bhh[4], bll[4];
                    ldsm4(bhh, va);
                    ldsm4(bll, va + 16384);
                    mma16816(oacc[2*g],   aPh, bhh[0], bhh[2]);
                    mma16816(oacc[2*g+1], aPh, bhh[1], bhh[3]);
                    mma16816(oacc[2*g],   aPl, bhh[0], bhh[2]);
                    mma16816(oacc[2*g+1], aPl, bhh[1], bhh[3]);
                    mma16816(oacc[2*g],   aPh, bll[0], bll[2]);
                    mma16816(oacc[2*g+1], aPh, bll[1], bll[3]);
                }
            }
        }
        __syncthreads();
        if (kb + 2 < nkb) issue_kv(kb + 2);
    }

    lp0 += __shfl_xor_sync(0xffffffffu, lp0, 1);
    lp0 += __shfl_xor_sync(0xffffffffu, lp0, 2);
    lp1 += __shfl_xor_sync(0xffffffffu, lp1, 1);
    lp1 += __shfl_xor_sync(0xffffffffu, lp1, 2);
    const float inv0 = 1.f / lp0, inv1 = 1.f / lp1;

    // ---- write O directly as bf16 hi|lo split (g_attnc) ----
    const size_t row = (size_t)b * SEQ + qb * 128 + w * 16 + (lane >> 2);
    const int colb = h * 128 + (lane & 3) * 2;
#pragma unroll
    for (int g = 0; g < 16; g++) {
        int col = colb + g * 8;
        float v0 = oacc[g][0] * inv0, v1 = oacc[g][1] * inv0;
        float v2 = oacc[g][2] * inv1, v3 = oacc[g][3] * inv1;
        unsigned short h0,h1,h2,h3,l0,l1,l2,l3;
        split1(v0,h0,l0); split1(v1,h1,l1);
        split1(v2,h2,l2); split1(v3,h3,l3);
        __nv_bfloat16* pa = g_attnc + row * K2 + col;
        *(ushort2*)pa          = make_ushort2(h0,h1);
        *(ushort2*)(pa + HID)  = make_ushort2(l0,l1);
        __nv_bfloat16* pb = pa + 8 * K2;
        *(ushort2*)pb          = make_ushort2(h2,h3);
        *(ushort2*)(pb + HID)  = make_ushort2(l2,l3);
    }
}

// ---------------- launch ----------------
extern "C" void kernel_launch(void* const* d_in, const int* in_sizes, int n_in,
                              void* d_out, int out_size)
{
    (void)in_sizes; (void)n_in; (void)out_size;
    const float* x       = (const float*)d_in[0];
    const float* w_qkv   = (const float*)d_in[1];
    const float* b_qkv   = (const float*)d_in[2];
    const float* w_dense = (const float*)d_in[3];
    const float* b_dense = (const float*)d_in[4];
    float* out = (float*)d_out;

    __nv_bfloat16 *xc, *wqkvc, *wdc, *attnc;
    cudaGetSymbolAddress((void**)&xc, g_xc);
    cudaGetSymbolAddress((void**)&wqkvc, g_wqkvc);
    cudaGetSymbolAddress((void**)&wdc, g_wdc);
    cudaGetSymbolAddress((void**)&attnc, g_attnc);

    cudaFuncSetAttribute(gemm_qkv_kernel,
                         cudaFuncAttributeMaxDynamicSharedMemorySize, GEMM_SMEM);
    cudaFuncSetAttribute(gemm_hmma_kernel,
                         cudaFuncAttributeMaxDynamicSharedMemorySize, GEMM_SMEM);
    cudaFuncSetAttribute(attn_hmma_kernel,
                         cudaFuncAttributeMaxDynamicSharedMemorySize, ATTN_SMEM);

    // split conversions (fp32 -> bf16 hi|lo)
    split_kernel<<<(MROWS * HID / 4 + 255) / 256, 256>>>(x, xc, MROWS);
    split_kernel<<<(HID3 * HID / 4 + 255) / 256, 256>>>(w_qkv, wqkvc, HID3);
    split_kernel<<<(HID  * HID / 4 + 255) / 256, 256>>>(w_dense, wdc, HID);

    // 1) QKV GEMM with fused operand-prep epilogue
    gemm_qkv_kernel<<<dim3(HID3 / 128, MROWS / 128), 256, GEMM_SMEM>>>(
        xc, wqkvc, b_qkv);

    // 2) HMMA flash attention (writes bf16 split directly)
    attn_hmma_kernel<<<dim3(16, NH, BATCH), 256, ATTN_SMEM>>>();

    // 3) out = attn @ Wdense^T + b
    gemm_hmma_kernel<<<dim3(HID / 128, MROWS / 128), 256, GEMM_SMEM>>>(
        attnc, wdc, b_dense, out, HID);
}